// round 8
// baseline (speedup 1.0000x reference)
#include <cuda_runtime.h>
#include <cstdint>

// ViewControlPreprocessor (non-causal path), GB300 sm_103a.
//   hidden_states: (1536, 21, 3072) f32
//   view_control_condition: (1, 81, 16) f32  -> 5KB L1-resident table
//   output: (1536, 21, 3200) f32
//
//   out[r, :3072]            = hidden[r, :]
//   out[r, 3072 + p*16 + c]  = vcc[max(4*(r%21)+p-8, 0), c],  p in [0,8)
//
// Roofline: compulsory 396MB read + 413MB write. Measured GB300 mixed-R/W
// plateau ~6.7 TB/s (84-85% of 8TB/s spec) — invariant across MLP (4 vs 8)
// and transport path (CE pitched D2D 3.5x worse; persistent grid worse).
// Marginal gradient observed: higher occupancy -> slightly higher DRAM%
// (62%->84.1%, 82.5%->84.9%). This round: finer 128-thread blocks for max
// resident CTAs and smoother tail drain.

static constexpr int T_Q     = 21;
static constexpr int ROWS    = 1536 * 21;          // 32256
static constexpr int HID_F4  = 3072 / 4;           // 768 float4 per row (hidden)
static constexpr int ROW_F4  = 800;                // float4 per output row
static constexpr int PAD_T   = 8;
static constexpr long long TOTAL_F4 = (long long)ROWS * ROW_F4;  // 25,804,800
static constexpr int THREADS = 128;
static constexpr int UNROLL  = 4;
// 25,804,800 / (128*4) = 50400 exactly -> predicate-free grid.
static constexpr int BLOCKS  = (int)(TOTAL_F4 / (THREADS * UNROLL));

__device__ __forceinline__ float4 fetch_one(const float4* __restrict__ hidden,
                                            const float4* __restrict__ vcc,
                                            int i)
{
    int row  = i / ROW_F4;          // compile-time-constant divide -> IMAD magic
    int col4 = i - row * ROW_F4;

    if (col4 < HID_F4) {
        // hidden_idx = row*768 + col4 = i - 32*row
        return __ldcs(&hidden[i - 32 * row]);   // streaming: read exactly once
    } else {
        int c4 = col4 - HID_F4;      // 0..31
        int p  = c4 >> 2;            // PAD_T slot (0..7)
        int q  = c4 & 3;             // float4 within 16-float channel row
        int t  = row % T_Q;          // compile-time-constant mod
        int j  = 4 * t + p;          // padded index 0..88
        int src = (j < PAD_T) ? 0 : (j - PAD_T);
        return __ldg(&vcc[src * 4 + q]);   // 5KB table, L1-resident
    }
}

__global__ void __launch_bounds__(THREADS)
vcp_fuse_kernel(const float4* __restrict__ hidden,
                const float4* __restrict__ vcc,
                float4* __restrict__ out)
{
    // Block covers 512 consecutive float4 (8KB dst span); each 128-thread
    // sweep is a contiguous, perfectly coalesced 2KB span. Warp spans never
    // straddle the hidden/tail boundary (768 and 800 are multiples of 32)
    // -> zero intra-warp divergence.
    int base = blockIdx.x * (THREADS * UNROLL) + threadIdx.x;

    float4 v[UNROLL];
    // Batch all loads first (per-thread MLP = 4), then all stores.
    #pragma unroll
    for (int u = 0; u < UNROLL; u++) {
        v[u] = fetch_one(hidden, vcc, base + u * THREADS);
    }
    #pragma unroll
    for (int u = 0; u < UNROLL; u++) {
        __stcs(&out[base + u * THREADS], v[u]);   // streaming store: never re-read
    }
}

extern "C" void kernel_launch(void* const* d_in, const int* in_sizes, int n_in,
                              void* d_out, int out_size)
{
    const float4* hidden = (const float4*)d_in[0];
    const float4* vcc    = (const float4*)d_in[1];
    float4* out = (float4*)d_out;

    vcp_fuse_kernel<<<BLOCKS, THREADS>>>(hidden, vcc, out);
}